// round 12
// baseline (speedup 1.0000x reference)
#include <cuda_runtime.h>
#include <cuda_pipeline.h>
#include <math.h>

#define Nn 16
#define Ss 4
#define Cc 128
#define Hh 36
#define Ww 36
#define Uu 8000
#define Rr 4
#define HW (Hh*Ww)
#define NKEY (37*37)   // 1369 bilinear cells
#define UT 8           // items per pipeline stage
#define SEG 6          // keys per thread in 256-thread scan

typedef unsigned long long u64t;

// ---- Blackwell packed-fp32 helpers (FFMA2 via PTX f32x2) -------------------
__device__ __forceinline__ u64t pack2(float lo, float hi) {
    u64t r;
    asm("mov.b64 %0, {%1, %2};" : "=l"(r) : "f"(lo), "f"(hi));
    return r;
}
__device__ __forceinline__ u64t fma2(u64t a, u64t b, u64t c) {
    u64t d;
    asm("fma.rn.f32x2 %0, %1, %2, %3;" : "=l"(d) : "l"(a), "l"(b), "l"(c));
    return d;
}
__device__ __forceinline__ u64t mul2(u64t a, u64t b) {
    u64t d;
    asm("mul.rn.f32x2 %0, %1, %2;" : "=l"(d) : "l"(a), "l"(b));
    return d;
}
__device__ __forceinline__ float hadd2(u64t a) {
    float lo, hi;
    asm("mov.b64 {%0, %1}, %2;" : "=f"(lo), "=f"(hi) : "l"(a));
    return lo + hi;
}

// Scratch (device globals — no runtime allocation)
__device__ float  g_coreT[(size_t)Nn*Ss*HW*Cc];   // [n][s][p][c], 42.5 MB
__device__ int2   g_off2[NKEY];                   // {start, end} per cell
__device__ int    g_sortedU[Uu];
__device__ float4 g_wts[Uu];                      // w00,w01,w10,w11 per sorted slot

// ---------------------------------------------------------------------------
// Fused prep: z < Nn*Ss -> transpose (2 c-groups per block, MLP=2),
//             z == Nn*Ss -> binsort (block 0,0 only)
// ---------------------------------------------------------------------------
__device__ __forceinline__ int cell_key_w(const float* pos, int u,
                                          float& wx, float& wy) {
    float x = ((pos[2*u]   + 1.0f) * (float)Ww - 1.0f) * 0.5f;
    float y = ((pos[2*u+1] + 1.0f) * (float)Hh - 1.0f) * 0.5f;
    float xf = floorf(x), yf = floorf(y);
    wx = x - xf; wy = y - yf;
    int kx = (int)xf; kx = max(-1, min(kx, Ww-1));
    int ky = (int)yf; ky = max(-1, min(ky, Hh-1));
    return (ky+1)*37 + (kx+1);
}

__global__ void __launch_bounds__(256)
prep_kernel(const float* __restrict__ core, const float* __restrict__ pos) {
    __shared__ float tile[2][32*32];     // transpose path (two c-groups)
    __shared__ int   hist[NKEY];         // binsort path
    __shared__ int   curs[NKEY];
    __shared__ int   wtot[8];

    int t = threadIdx.x;

    if (blockIdx.z == (unsigned)(Nn*Ss)) {
        // ---------------- binsort (single block) ----------------
        if (blockIdx.x != 0 || blockIdx.y != 0) return;

        for (int i = t; i < NKEY; i += 256) hist[i] = 0;
        __syncthreads();

        for (int u = t; u < Uu; u += 256) {
            float wx, wy;
            int key = cell_key_w(pos, u, wx, wy);
            atomicAdd(&hist[key], 1);
        }
        __syncthreads();

        int lane = t & 31, wid = t >> 5;
        int lv[SEG];
        int run = 0;
        #pragma unroll
        for (int k = 0; k < SEG; k++) {
            int i = t*SEG + k;
            run += (i < NKEY) ? hist[i] : 0;
            lv[k] = run;
        }
        int tot = run;
        int inc = tot;
        #pragma unroll
        for (int d = 1; d < 32; d <<= 1) {
            int y = __shfl_up_sync(0xffffffffu, inc, d);
            if (lane >= d) inc += y;
        }
        if (lane == 31) wtot[wid] = inc;
        __syncthreads();
        if (t == 0) {
            int s = 0;
            #pragma unroll
            for (int w = 0; w < 8; w++) { int v = wtot[w]; wtot[w] = s; s += v; }
        }
        __syncthreads();
        int exc = wtot[wid] + (inc - tot);
        #pragma unroll
        for (int k = 0; k < SEG; k++) {
            int i = t*SEG + k;
            if (i < NKEY) {
                int cnt_i = hist[i];
                int off   = exc + lv[k] - cnt_i;
                g_off2[i] = make_int2(off, off + cnt_i);
                curs[i]   = off;
            }
        }
        __syncthreads();

        for (int u = t; u < Uu; u += 256) {
            float wx, wy;
            int key = cell_key_w(pos, u, wx, wy);
            int p = atomicAdd(&curs[key], 1);
            g_sortedU[p] = u;
            g_wts[p] = make_float4((1.0f-wx)*(1.0f-wy), wx*(1.0f-wy),
                                   (1.0f-wx)*wy,        wx*wy);
        }
        return;
    }

    // ---------------- transpose: 2 c-groups x 32 px, XOR swizzle ----------------
    int ns = blockIdx.z;
    int p0 = blockIdx.x * 32;

    int cl = t >> 3, q = t & 7;
    int p  = p0 + q*4;
    if (p < HW) {
        #pragma unroll
        for (int g = 0; g < 2; g++) {
            int c = blockIdx.y*64 + g*32 + cl;
            float4 v = *(const float4*)(core + ((size_t)(ns*Cc + c))*HW + p);
            tile[g][cl*32 + ((q*4+0) ^ cl)] = v.x;
            tile[g][cl*32 + ((q*4+1) ^ cl)] = v.y;
            tile[g][cl*32 + ((q*4+2) ^ cl)] = v.z;
            tile[g][cl*32 + ((q*4+3) ^ cl)] = v.w;
        }
    }
    __syncthreads();

    int pl = t >> 3, cq = t & 7;
    int pg = p0 + pl;
    if (pg < HW) {
        #pragma unroll
        for (int g = 0; g < 2; g++) {
            float4 o;
            o.x = tile[g][(cq*4+0)*32 + (pl ^ (cq*4+0))];
            o.y = tile[g][(cq*4+1)*32 + (pl ^ (cq*4+1))];
            o.z = tile[g][(cq*4+2)*32 + (pl ^ (cq*4+2))];
            o.w = tile[g][(cq*4+3)*32 + (pl ^ (cq*4+3))];
            *(float4*)(g_coreT + ((size_t)ns*HW + pg)*Cc
                       + blockIdx.y*64 + g*32 + cq*4) = o;
        }
    }
}

// ---------------------------------------------------------------------------
// Main: grid (cell, s). Block = 8 warps; warp w serves n = {2w, 2w+1};
// lane = 4-channel chunk. f32x2 packed FFMA; one feature LDS.128 feeds both
// n's. UT=8 -> most blocks are single-tile (minimal sync/wait overhead).
// ---------------------------------------------------------------------------
__global__ void __launch_bounds__(256, 4)
main_kernel(const float* __restrict__ feature,
            const float* __restrict__ bias,
            float* __restrict__ out)
{
    int cell = blockIdx.x;
    int s    = blockIdx.y;
    int2 se  = g_off2[cell];          // one LDG.64 for {start, end}
    int start = se.x, end = se.y;
    int cnt   = end - start;
    if (cnt == 0) return;

    int cx = cell % 37 - 1;
    int cy = cell / 37 - 1;
    int x0 = max(cx, 0), x1 = min(cx+1, Ww-1);
    int y0 = max(cy, 0), y1 = min(cy+1, Hh-1);
    int pixs[4] = { y0*Ww + x0, y0*Ww + x1, y1*Ww + x0, y1*Ww + x1 };

    int t    = threadIdx.x;
    int wid  = t >> 5;
    int lane = t & 31;

    __shared__ float4 smF[2][UT*128];   // feature tiles (2 x 16 KB)
    __shared__ float4 smW[2][UT];       // bilinear weights
    __shared__ float4 smB[2][UT];       // bias
    __shared__ int    smU[2][UT];       // u indices

    int nTiles = (cnt + UT - 1) / UT;

    auto issue = [&](int tk, int bufi) {
        int tbase = start + tk*UT;
        int tcnt  = min(UT, end - tbase);
        #pragma unroll
        for (int e2 = 0; e2 < UT*128; e2 += 256) {
            int e = e2 + t;
            if (e < tcnt*128) {
                int u = g_sortedU[tbase + (e >> 7)];
                const float4* src = (const float4*)feature
                                  + (((size_t)(s*Uu + u)) << 7) + (e & 127);
                __pipeline_memcpy_async(&smF[bufi][e], src, 16);
            }
        }
        if (t < tcnt) {
            int u = g_sortedU[tbase + t];
            __pipeline_memcpy_async(&smW[bufi][t], &g_wts[tbase + t], 16);
            __pipeline_memcpy_async(&smB[bufi][t],
                                    (const float4*)bias + (size_t)(s*Uu + u), 16);
            __pipeline_memcpy_async(&smU[bufi][t], &g_sortedU[tbase + t], 4);
        }
    };

    issue(0, 0);
    __pipeline_commit();

    // One-time corner load as packed f32 pairs: 2n x 4 corners x 2 pairs
    u64t cvp[2][4][2];
    #pragma unroll
    for (int nn = 0; nn < 2; nn++) {
        int n = wid*2 + nn;
        const float* baseT = g_coreT + ((size_t)(n*Ss + s))*HW*Cc + lane*4;
        #pragma unroll
        for (int k = 0; k < 4; k++) {
            ulonglong2 v = *(const ulonglong2*)(baseT + (size_t)pixs[k]*Cc);
            cvp[nn][k][0] = v.x;
            cvp[nn][k][1] = v.y;
        }
    }

    for (int tk = 0; tk < nTiles; tk++) {
        int cur = tk & 1;
        if (tk + 1 < nTiles) {
            issue(tk + 1, cur ^ 1);
            __pipeline_commit();
            __pipeline_wait_prior(1);
        } else {
            __pipeline_wait_prior(0);
        }
        __syncthreads();

        int tcnt = min(UT, cnt - tk*UT);

        #pragma unroll
        for (int ul = 0; ul < UT; ul++) {
            if (ul >= tcnt) break;

            float4 w = smW[cur][ul];
            u64t wp0 = pack2(w.x, w.x);
            u64t wp1 = pack2(w.y, w.y);
            u64t wp2 = pack2(w.z, w.z);
            u64t wp3 = pack2(w.w, w.w);

            // bilinear-combined corner pairs per n
            u64t sv[2][2];
            #pragma unroll
            for (int nn = 0; nn < 2; nn++) {
                #pragma unroll
                for (int pr = 0; pr < 2; pr++) {
                    sv[nn][pr] = fma2(wp0, cvp[nn][0][pr],
                                 fma2(wp1, cvp[nn][1][pr],
                                 fma2(wp2, cvp[nn][2][pr],
                                 mul2(wp3, cvp[nn][3][pr]))));
                }
            }

            // dots: one LDS.128 per r feeds both n's
            const ulonglong2* fbu = (const ulonglong2*)&smF[cur][ul*128];
            float a00, a01, a02, a03, a10, a11, a12, a13;
            {
                ulonglong2 f;
                f = fbu[0*32 + lane];
                a00 = hadd2(fma2(f.x, sv[0][0], mul2(f.y, sv[0][1])));
                a10 = hadd2(fma2(f.x, sv[1][0], mul2(f.y, sv[1][1])));
                f = fbu[1*32 + lane];
                a01 = hadd2(fma2(f.x, sv[0][0], mul2(f.y, sv[0][1])));
                a11 = hadd2(fma2(f.x, sv[1][0], mul2(f.y, sv[1][1])));
                f = fbu[2*32 + lane];
                a02 = hadd2(fma2(f.x, sv[0][0], mul2(f.y, sv[0][1])));
                a12 = hadd2(fma2(f.x, sv[1][0], mul2(f.y, sv[1][1])));
                f = fbu[3*32 + lane];
                a03 = hadd2(fma2(f.x, sv[0][0], mul2(f.y, sv[0][1])));
                a13 = hadd2(fma2(f.x, sv[1][0], mul2(f.y, sv[1][1])));
            }

            // staged 9-SHFL reduce: lane bits -> b0,b1 = r, b2 = n-parity
            bool b0 = lane & 1;
            float k0_01 = b0 ? a01 : a00, s0_01 = b0 ? a00 : a01;
            k0_01 += __shfl_xor_sync(0xffffffffu, s0_01, 1);
            float k0_23 = b0 ? a03 : a02, s0_23 = b0 ? a02 : a03;
            k0_23 += __shfl_xor_sync(0xffffffffu, s0_23, 1);
            float k1_01 = b0 ? a11 : a10, s1_01 = b0 ? a10 : a11;
            k1_01 += __shfl_xor_sync(0xffffffffu, s1_01, 1);
            float k1_23 = b0 ? a13 : a12, s1_23 = b0 ? a12 : a13;
            k1_23 += __shfl_xor_sync(0xffffffffu, s1_23, 1);

            bool b1 = lane & 2;
            float v0 = b1 ? k0_23 : k0_01, vs0 = b1 ? k0_01 : k0_23;
            v0 += __shfl_xor_sync(0xffffffffu, vs0, 2);
            float v1 = b1 ? k1_23 : k1_01, vs1 = b1 ? k1_01 : k1_23;
            v1 += __shfl_xor_sync(0xffffffffu, vs1, 2);

            bool b2 = lane & 4;
            float z = b2 ? v1 : v0, zs = b2 ? v0 : v1;
            z += __shfl_xor_sync(0xffffffffu, zs, 4);
            z += __shfl_xor_sync(0xffffffffu, z, 8);
            z += __shfl_xor_sync(0xffffffffu, z, 16);

            if (lane < 8) {
                int r  = lane & 3;
                int n  = wid*2 + ((lane >> 2) & 1);
                int u  = smU[cur][ul];
                float bb = ((const float*)&smB[cur][ul])[r];
                out[(((size_t)(n*Ss + s))*Uu + u)*Rr + r] = z + bb;
            }
        }
        __syncthreads();   // buffer reads done before refill
    }
}

// ---------------------------------------------------------------------------
extern "C" void kernel_launch(void* const* d_in, const int* in_sizes, int n_in,
                              void* d_out, int out_size) {
    const float* core      = (const float*)d_in[0];
    const float* positions = (const float*)d_in[1];
    const float* feature   = (const float*)d_in[2];
    const float* bias      = (const float*)d_in[3];
    float* out = (float*)d_out;

    dim3 tg((HW + 31)/32, Cc/64, Nn*Ss + 1);   // last z-slice: binsort block
    prep_kernel<<<tg, 256>>>(core, positions);

    main_kernel<<<dim3(NKEY, Ss), 256>>>(feature, bias, out);
}